// round 3
// baseline (speedup 1.0000x reference)
#include <cuda_runtime.h>
#include <cuda_bf16.h>
#include <math.h>

#define B_    32
#define H_    32
#define D_    128
#define HID_  4096
#define TH_   12288      // 3*HID
#define BS_   64
#define NBLK_ 16

__device__ float g_qkv[B_ * TH_];    // [b][j] ; j<4096 q, 4096..8191 k, 8192.. v
__device__ float g_attn[B_ * HID_];  // [b][h*128+d]

typedef unsigned long long u64;

// ---- packed f32x2 helpers (sm_103a dual-FP32 path) ----
__device__ __forceinline__ u64 pack2(float lo, float hi) {
    u64 r; asm("mov.b64 %0, {%1, %2};" : "=l"(r) : "f"(lo), "f"(hi)); return r;
}
__device__ __forceinline__ u64 fma2(u64 a, u64 b, u64 c) {
    u64 d; asm("fma.rn.f32x2 %0, %1, %2, %3;" : "=l"(d) : "l"(a), "l"(b), "l"(c)); return d;
}
__device__ __forceinline__ float hadd2(u64 a) {
    float lo, hi; asm("mov.b64 {%0, %1}, %2;" : "=f"(lo), "=f"(hi) : "l"(a)); return lo + hi;
}

// ---------------------------------------------------------------------------
// Kernel 1: qkv = hidden @ W_pack   (32x4096 @ 4096x12288), f32x2 over k.
// grid 384, block 128: 32 columns/block; thread = (col lane, batch-group of 8)
// ---------------------------------------------------------------------------
#define KCHUNK 256
__global__ __launch_bounds__(128) void qkv_kernel(const float* __restrict__ hidden,
                                                  const float* __restrict__ W) {
    __shared__ float sh[32][KCHUNK];     // 32 KB
    const int j  = blockIdx.x * 32 + (threadIdx.x & 31);
    const int bg = (threadIdx.x >> 5) * 8;

    u64 accA[8], accB[8];
#pragma unroll
    for (int i = 0; i < 8; i++) { accA[i] = 0ull; accB[i] = 0ull; }

    const float* wbase = W + j;
    for (int kc = 0; kc < HID_; kc += KCHUNK) {
        __syncthreads();
        // fully unrolled tile load: 16 LDG.128 in flight per thread
#pragma unroll
        for (int t = 0; t < 16; t++) {
            int idx = threadIdx.x + t * 128;
            int b   = idx / (KCHUNK / 4);
            int kk  = (idx % (KCHUNK / 4)) * 4;
            *(float4*)&sh[b][kk] = *(const float4*)&hidden[b * HID_ + kc + kk];
        }
        __syncthreads();

        const float* wp = wbase + (size_t)kc * TH_;
#pragma unroll 4
        for (int k = 0; k < KCHUNK; k += 4) {
            float w0 = wp[0];
            float w1 = wp[TH_];
            float w2 = wp[2 * TH_];
            float w3 = wp[3 * TH_];
            wp += 4 * (size_t)TH_;
            u64 w01 = pack2(w0, w1);
            u64 w23 = pack2(w2, w3);
#pragma unroll
            for (int bb = 0; bb < 8; bb++) {
                ulonglong2 s2 = *(const ulonglong2*)&sh[bg + bb][k];   // broadcast
                accA[bb] = fma2(s2.x, w01, accA[bb]);
                accB[bb] = fma2(s2.y, w23, accB[bb]);
            }
        }
    }
#pragma unroll
    for (int bb = 0; bb < 8; bb++)
        g_qkv[(bg + bb) * TH_ + j] = hadd2(accA[bb]) + hadd2(accB[bb]);
}

// ---------------------------------------------------------------------------
// Kernel 2: RoPE on q and k in g_qkv. grid (32, 64): y = part*32 + h. block 128.
// ---------------------------------------------------------------------------
__global__ __launch_bounds__(128) void rope_kernel(const int* __restrict__ hist) {
    const int b    = blockIdx.x;
    const int part = blockIdx.y >> 5;
    const int h    = blockIdx.y & 31;
    const int d    = threadIdx.x;
    const int pos  = hist[b];
    const int i    = d & 63;

    double invd = exp(-(double)i / 64.0 * 9.210340371976184);  // ln(10000)
    double angd = fmod((double)pos * invd, 6.283185307179586476925286766559);
    float c = cosf((float)angd);
    float s = sinf((float)angd);

    float* p = &g_qkv[b * TH_ + part * HID_ + h * D_];
    float x  = p[d];
    float xr = (d < 64) ? -p[d + 64] : p[d - 64];
    __syncthreads();
    p[d] = x * c + xr * s;
}

// ---------------------------------------------------------------------------
// Kernel 3: attention, two-phase (no online-softmax serial chain).
// grid = B*H blocks, 256 threads.
// Phase 1: warps compute all scores -> smem (coalesced K stream).
// Phase 2: thread = d channel, coalesced V stream, p[s] broadcast from smem.
// s == hist uses fresh RoPE'd k / raw v from g_qkv (ref writes cache first).
// ---------------------------------------------------------------------------
__global__ __launch_bounds__(256) void attn_kernel(const float* __restrict__ kcache,
                                                   const float* __restrict__ vcache,
                                                   const int* __restrict__ hist,
                                                   const int* __restrict__ boff) {
    const int b = blockIdx.x >> 5;
    const int h = blockIdx.x & 31;
    const int tid  = threadIdx.x;
    const int lane = tid & 31;
    const int wid  = tid >> 5;

    __shared__ int   s_blk[NBLK_];
    __shared__ float s_sc[1024];
    __shared__ float s_red[8];
    __shared__ float s_half[128];

    if (tid < NBLK_) s_blk[tid] = boff[b * NBLK_ + tid];
    __syncthreads();

    const int pos = hist[b];
    const float scale = 0.08838834764831845f;  // 1/sqrt(128)
    const float4 q4 = *(const float4*)&g_qkv[b * TH_ + h * D_ + lane * 4];

    // ---- phase 1: scores ----
    float mloc = -1e30f;
    int s = wid;
    for (; s + 8 < pos; s += 16) {
        int a0 = ((s_blk[s >> 6] * BS_ + (s & 63)) * H_ + h) * D_;
        int s1 = s + 8;
        int a1 = ((s_blk[s1 >> 6] * BS_ + (s1 & 63)) * H_ + h) * D_;
        float4 k0 = *(const float4*)&kcache[a0 + lane * 4];
        float4 k1 = *(const float4*)&kcache[a1 + lane * 4];
        float d0 = q4.x * k0.x + q4.y * k0.y + q4.z * k0.z + q4.w * k0.w;
        float d1 = q4.x * k1.x + q4.y * k1.y + q4.z * k1.z + q4.w * k1.w;
#pragma unroll
        for (int o = 16; o > 0; o >>= 1) {
            d0 += __shfl_xor_sync(0xffffffffu, d0, o);
            d1 += __shfl_xor_sync(0xffffffffu, d1, o);
        }
        d0 *= scale; d1 *= scale;
        mloc = fmaxf(mloc, fmaxf(d0, d1));
        if (lane == 0) { s_sc[s] = d0; s_sc[s1] = d1; }
    }
    for (; s < pos; s += 8) {
        int a0 = ((s_blk[s >> 6] * BS_ + (s & 63)) * H_ + h) * D_;
        float4 k0 = *(const float4*)&kcache[a0 + lane * 4];
        float d0 = q4.x * k0.x + q4.y * k0.y + q4.z * k0.z + q4.w * k0.w;
#pragma unroll
        for (int o = 16; o > 0; o >>= 1) d0 += __shfl_xor_sync(0xffffffffu, d0, o);
        d0 *= scale;
        mloc = fmaxf(mloc, d0);
        if (lane == 0) s_sc[s] = d0;
    }
    if ((pos & 7) == wid) {      // fresh k at s == pos
        const float* kp = &g_qkv[b * TH_ + HID_ + h * D_];
        float4 k0 = *(const float4*)&kp[lane * 4];
        float d0 = q4.x * k0.x + q4.y * k0.y + q4.z * k0.z + q4.w * k0.w;
#pragma unroll
        for (int o = 16; o > 0; o >>= 1) d0 += __shfl_xor_sync(0xffffffffu, d0, o);
        d0 *= scale;
        mloc = fmaxf(mloc, d0);
        if (lane == 0) s_sc[pos] = d0;
    }

    if (lane == 0) s_red[wid] = mloc;
    __syncthreads();
    float M = -1e30f;
#pragma unroll
    for (int w = 0; w < 8; w++) M = fmaxf(M, s_red[w]);

    // exp pass + partial sum
    float lsum = 0.f;
    for (int i = tid; i <= pos; i += 256) {
        float p = __expf(s_sc[i] - M);
        s_sc[i] = p;
        lsum += p;
    }
#pragma unroll
    for (int o = 16; o > 0; o >>= 1) lsum += __shfl_xor_sync(0xffffffffu, lsum, o);
    __syncthreads();                 // s_red reuse + s_sc visibility
    if (lane == 0) s_red[wid] = lsum;
    __syncthreads();
    float L = 0.f;
#pragma unroll
    for (int w = 0; w < 8; w++) L += s_red[w];
    const float invL = 1.f / L;

    // ---- phase 2: out[d] = sum_s p[s] * v[s][d], coalesced over d ----
    const int d    = tid & 127;
    const int half = tid >> 7;
    float acc = 0.f;
#pragma unroll 4
    for (int s2 = half; s2 < pos; s2 += 2) {
        int base = ((s_blk[s2 >> 6] * BS_ + (s2 & 63)) * H_ + h) * D_;
        acc += s_sc[s2] * vcache[base + d];
    }
    if ((pos & 1) == half)
        acc += s_sc[pos] * g_qkv[b * TH_ + 2 * HID_ + h * D_ + d];

    if (half == 0) s_half[d] = acc;
    __syncthreads();
    if (half == 1)
        g_attn[b * HID_ + h * D_ + d] = (acc + s_half[d]) * invL;
}

// ---------------------------------------------------------------------------
// Kernel 4: out = attn @ Wo^T. block 128 (4 warps), warp -> 4 rows x 16 batches.
// grid 512 = 256 row-tiles x 2 batch-halves. No min-blocks cap -> no spills.
// ---------------------------------------------------------------------------
__global__ __launch_bounds__(128) void oproj_kernel(const float* __restrict__ Wo,
                                                    float* __restrict__ out) {
    __shared__ float s_attn[16][256];    // 16 KB
    const int lane = threadIdx.x & 31;
    const int wid  = threadIdx.x >> 5;
    const int tile = blockIdx.x >> 1;         // 0..255
    const int bh   = (blockIdx.x & 1) * 16;   // batch half
    const int i0   = tile * 16 + wid * 4;

    float acc[4][16];
#pragma unroll
    for (int r = 0; r < 4; r++)
#pragma unroll
        for (int b = 0; b < 16; b++) acc[r][b] = 0.f;

    for (int jt = 0; jt < HID_; jt += 256) {
        __syncthreads();
#pragma unroll
        for (int t = 0; t < 8; t++) {
            int idx = threadIdx.x + t * 128;
            int b   = idx >> 6;
            int jj  = (idx & 63) << 2;
            *(float4*)&s_attn[b][jj] = *(const float4*)&g_attn[(bh + b) * HID_ + jt + jj];
        }
        __syncthreads();

        const float* w = Wo + (size_t)i0 * HID_ + jt;
#pragma unroll
        for (int part = 0; part < 2; part++) {
            int j0 = part * 128 + lane * 4;
            float4 w0 = *(const float4*)&w[j0];
            float4 w1 = *(const float4*)&w[HID_ + j0];
            float4 w2 = *(const float4*)&w[2 * HID_ + j0];
            float4 w3 = *(const float4*)&w[3 * HID_ + j0];
#pragma unroll
            for (int b = 0; b < 16; b++) {
                float4 a = *(const float4*)&s_attn[b][j0];
                acc[0][b] += a.x * w0.x + a.y * w0.y + a.z * w0.z + a.w * w0.w;
                acc[1][b] += a.x * w1.x + a.y * w1.y + a.z * w1.z + a.w * w1.w;
                acc[2][b] += a.x * w2.x + a.y * w2.y + a.z * w2.z + a.w * w2.w;
                acc[3][b] += a.x * w3.x + a.y * w3.y + a.z * w3.z + a.w * w3.w;
            }
        }
    }

#pragma unroll
    for (int r = 0; r < 4; r++) {
        float res = 0.f;
#pragma unroll
        for (int b = 0; b < 16; b++) {
            float v = acc[r][b];
#pragma unroll
            for (int o = 16; o > 0; o >>= 1) v += __shfl_xor_sync(0xffffffffu, v, o);
            if (lane == b) res = v;
        }
        if (lane < 16) out[(bh + lane) * HID_ + i0 + r] = res;
    }
}

// ---------------------------------------------------------------------------
extern "C" void kernel_launch(void* const* d_in, const int* in_sizes, int n_in,
                              void* d_out, int out_size) {
    const float* hidden = (const float*)d_in[0];
    const float* W      = (const float*)d_in[1];
    const float* Wo     = (const float*)d_in[2];
    const float* kcache = (const float*)d_in[3];
    const float* vcache = (const float*)d_in[4];
    const int*   hist   = (const int*)d_in[5];
    const int*   boff   = (const int*)d_in[6];
    float*       out    = (float*)d_out;

    qkv_kernel<<<TH_ / 32, 128>>>(hidden, W);
    rope_kernel<<<dim3(B_, 2 * H_), 128>>>(hist);
    attn_kernel<<<B_ * H_, 256>>>(kcache, vcache, hist, boff);
    oproj_kernel<<<512, 128>>>(Wo, out);
}